// round 1
// baseline (speedup 1.0000x reference)
#include <cuda_runtime.h>
#include <cuda_bf16.h>
#include <math.h>

// Problem constants
#define B_  32
#define S_  4096
#define D_  512
#define H_  512
#define M_  (B_ * S_)      // 131072 rows of the big GEMM

// GEMM tiling
#define BM 128
#define BN 128
#define BK 16
#define TM 8
#define TN 8

// ctx split
#define SPLIT 32
#define S_PER_SPLIT (S_ / SPLIT)   // 128

// ---------------- scratch (device globals: no allocation allowed) -------------
__device__ float g_t[B_ * H_];            // t[b,h]
__device__ float g_e[B_ * S_];            // pre-softmax logits
__device__ float g_ctx[B_ * SPLIT * D_];  // ctx partial sums

// robust tanh: exact limits at +/-inf, ~1e-7 rel err, fast-math safe
__device__ __forceinline__ float tanh_acc(float x) {
    return 1.0f - 2.0f / (expf(2.0f * x) + 1.0f);
}

// ---------------- K1: t[b,h] = sum_d targ[b,d] * W[h, d] ----------------------
__global__ __launch_bounds__(512) void t_kernel(const float* __restrict__ targ,
                                                const float* __restrict__ W) {
    __shared__ float ts[D_];
    int b = blockIdx.x;
    int h = threadIdx.x;
    ts[h] = targ[b * D_ + h];
    __syncthreads();
    const float* wr = W + (size_t)h * (2 * D_);   // row h, cols [0, D)
    float s = 0.0f;
#pragma unroll 8
    for (int d = 0; d < D_; d += 4) {
        float4 w4 = *(const float4*)(wr + d);
        s += ts[d] * w4.x + ts[d + 1] * w4.y + ts[d + 2] * w4.z + ts[d + 3] * w4.w;
    }
    g_t[b * H_ + h] = s;
}

// ---------------- K2: fused GEMM + tanh + V-dot -> e ---------------------------
// e[m] = sum_h V[h] * tanh( t[b,h] + sum_d src[m,d] * W[h, D + d] )
// A = src [M, 512] row-major; B = Ws rows (stride 1024, offset 512)
__global__ __launch_bounds__(256) void gemm_e_kernel(const float* __restrict__ src,
                                                     const float* __restrict__ W,
                                                     const float* __restrict__ V) {
    __shared__ float As[BK][BM];
    __shared__ float Bs[BK][BN];
    __shared__ float t_s[BN];
    __shared__ float v_s[BN];
    __shared__ float e_s[BM];

    const int tid = threadIdx.x;
    const int m_base = blockIdx.x * BM;
    const int b = m_base / S_;                  // 128 | 4096 -> single b per block
    const float* A = src + (size_t)m_base * D_;

    const int tx = tid & 15;       // column group (n)
    const int ty = tid >> 4;       // row group (m)

    if (tid < BM) e_s[tid] = 0.0f;

    float acc[TM][TN];

    for (int nc = 0; nc < H_ / BN; ++nc) {
        const int n_base = nc * BN;
        __syncthreads();   // previous epilogue done reading t_s/v_s; e_s init visible
        if (tid < BN) {
            t_s[tid] = g_t[b * H_ + n_base + tid];
            v_s[tid] = V[n_base + tid];
        }
#pragma unroll
        for (int i = 0; i < TM; ++i)
#pragma unroll
            for (int j = 0; j < TN; ++j) acc[i][j] = 0.0f;

        for (int kb = 0; kb < D_; kb += BK) {
            __syncthreads();  // previous compute done before overwrite
#pragma unroll
            for (int i = 0; i < 2; ++i) {
                int idx = tid * 2 + i;       // 0..511
                int row = idx >> 2;          // 0..127
                int c4  = (idx & 3) * 4;     // 0,4,8,12
                float4 av = *(const float4*)(A + (size_t)row * D_ + kb + c4);
                As[c4 + 0][row] = av.x;
                As[c4 + 1][row] = av.y;
                As[c4 + 2][row] = av.z;
                As[c4 + 3][row] = av.w;
                float4 bv = *(const float4*)(W + (size_t)(n_base + row) * (2 * D_) + D_ + kb + c4);
                Bs[c4 + 0][row] = bv.x;
                Bs[c4 + 1][row] = bv.y;
                Bs[c4 + 2][row] = bv.z;
                Bs[c4 + 3][row] = bv.w;
            }
            __syncthreads();
#pragma unroll
            for (int k = 0; k < BK; ++k) {
                float4 a0 = *(const float4*)&As[k][ty * 8];
                float4 a1 = *(const float4*)&As[k][ty * 8 + 4];
                float4 b0 = *(const float4*)&Bs[k][tx * 8];
                float4 b1 = *(const float4*)&Bs[k][tx * 8 + 4];
                float a[TM] = {a0.x, a0.y, a0.z, a0.w, a1.x, a1.y, a1.z, a1.w};
                float bb[TN] = {b0.x, b0.y, b0.z, b0.w, b1.x, b1.y, b1.z, b1.w};
#pragma unroll
                for (int i = 0; i < TM; ++i)
#pragma unroll
                    for (int j = 0; j < TN; ++j) acc[i][j] = fmaf(a[i], bb[j], acc[i][j]);
            }
        }
        // epilogue: tanh + V-weighted partial sums, reduce over tx lanes (16-group)
#pragma unroll
        for (int i = 0; i < TM; ++i) {
            float p = 0.0f;
#pragma unroll
            for (int j = 0; j < TN; ++j) {
                float x = acc[i][j] + t_s[tx * 8 + j];
                p = fmaf(v_s[tx * 8 + j], tanh_acc(x), p);
            }
            // butterfly within the 16-lane tx group (lane = (ty&1)*16 + tx)
            p += __shfl_xor_sync(0xffffffffu, p, 8);
            p += __shfl_xor_sync(0xffffffffu, p, 4);
            p += __shfl_xor_sync(0xffffffffu, p, 2);
            p += __shfl_xor_sync(0xffffffffu, p, 1);
            if (tx == 0) e_s[ty * 8 + i] += p;   // unique owner per row: race-free
        }
    }
    __syncthreads();
    if (tid < BM) g_e[m_base + tid] = e_s[tid];
}

// ---------------- K3: softmax over s (per b), write att to output --------------
__global__ __launch_bounds__(256) void softmax_kernel(const float* __restrict__ mask,
                                                      float* __restrict__ out_att) {
    const int b = blockIdx.x;
    const int tid = threadIdx.x;
    const float* e = g_e + (size_t)b * S_;
    __shared__ float red[8];

    float vals[16];
    float mx = -1e30f;
#pragma unroll
    for (int i = 0; i < 16; ++i) {
        vals[i] = e[tid + i * 256];
        mx = fmaxf(mx, vals[i]);
    }
#pragma unroll
    for (int o = 16; o >= 1; o >>= 1) mx = fmaxf(mx, __shfl_xor_sync(0xffffffffu, mx, o));
    if ((tid & 31) == 0) red[tid >> 5] = mx;
    __syncthreads();
    float M = red[0];
#pragma unroll
    for (int i = 1; i < 8; ++i) M = fmaxf(M, red[i]);
    __syncthreads();   // everyone read M before red reuse

    float sum = 0.0f;
#pragma unroll
    for (int i = 0; i < 16; ++i) {
        vals[i] = expf(vals[i] - M);
        sum += vals[i];
    }
#pragma unroll
    for (int o = 16; o >= 1; o >>= 1) sum += __shfl_xor_sync(0xffffffffu, sum, o);
    if ((tid & 31) == 0) red[tid >> 5] = sum;
    __syncthreads();
    float Ssum = 0.0f;
#pragma unroll
    for (int i = 0; i < 8; ++i) Ssum += red[i];

    const float inv = 1.0f / Ssum;
    const float* mrow = mask + (size_t)b * S_;
    float* orow = out_att + (size_t)b * S_;
#pragma unroll
    for (int i = 0; i < 16; ++i) {
        int s = tid + i * 256;
        orow[s] = vals[i] * inv * mrow[s];
    }
}

// ---------------- K4: ctx partials: g_ctx[b,sp,d] = sum_{s in split} att*src ---
__global__ __launch_bounds__(512) void ctx_partial_kernel(const float* __restrict__ src,
                                                          const float* __restrict__ att) {
    __shared__ float aw[S_PER_SPLIT];
    const int b = blockIdx.x;
    const int sp = blockIdx.y;
    const int tid = threadIdx.x;
    if (tid < S_PER_SPLIT) aw[tid] = att[(size_t)b * S_ + sp * S_PER_SPLIT + tid];
    __syncthreads();

    const float* p = src + ((size_t)b * S_ + (size_t)sp * S_PER_SPLIT) * D_ + tid;
    float a0 = 0.f, a1 = 0.f, a2 = 0.f, a3 = 0.f;
#pragma unroll 4
    for (int s = 0; s < S_PER_SPLIT; s += 4) {
        a0 = fmaf(aw[s + 0], p[(size_t)(s + 0) * D_], a0);
        a1 = fmaf(aw[s + 1], p[(size_t)(s + 1) * D_], a1);
        a2 = fmaf(aw[s + 2], p[(size_t)(s + 2) * D_], a2);
        a3 = fmaf(aw[s + 3], p[(size_t)(s + 3) * D_], a3);
    }
    g_ctx[((size_t)b * SPLIT + sp) * D_ + tid] = (a0 + a1) + (a2 + a3);
}

// ---------------- K5: reduce partials + residual -> hidden_output --------------
__global__ __launch_bounds__(512) void reduce_kernel(const float* __restrict__ targ,
                                                     float* __restrict__ out_hidden) {
    const int b = blockIdx.x;
    const int d = threadIdx.x;
    float s = targ[b * D_ + d];
#pragma unroll
    for (int sp = 0; sp < SPLIT; ++sp) s += g_ctx[((size_t)b * SPLIT + sp) * D_ + d];
    out_hidden[b * D_ + d] = s;
}

// ------------------------------- launcher --------------------------------------
extern "C" void kernel_launch(void* const* d_in, const int* in_sizes, int n_in,
                              void* d_out, int out_size) {
    const float* targ = (const float*)d_in[0];   // (B, D)
    const float* src  = (const float*)d_in[1];   // (B, S, D)
    const float* mask = (const float*)d_in[2];   // (B, S)
    const float* W    = (const float*)d_in[3];   // (D, 2D)
    const float* V    = (const float*)d_in[4];   // (D,)

    float* out = (float*)d_out;
    float* out_att    = out;             // att_weights (B, S) first
    float* out_hidden = out + B_ * S_;   // hidden_output (B, D) second

    t_kernel<<<B_, D_>>>(targ, W);
    gemm_e_kernel<<<M_ / BM, 256>>>(src, W, V);
    softmax_kernel<<<B_, 256>>>(mask, out_att);
    dim3 g4(B_, SPLIT);
    ctx_partial_kernel<<<g4, D_>>>(src, out_att);
    reduce_kernel<<<B_, D_>>>(targ, out_hidden);
}

// round 3
// speedup vs baseline: 1.6158x; 1.6158x over previous
#include <cuda_runtime.h>
#include <cuda_bf16.h>
#include <stdint.h>
#include <math.h>

// ---------------- problem constants ----------------
#define B_  32
#define S_  4096
#define D_  512
#define H_  512
#define M_  (B_ * S_)

#define SPLIT 32
#define S_PER_SPLIT 128

// gemm_e tiling
#define MT   64            // M rows per CTA
#define NCH  64            // N chunk
#define KCH  128           // K chunk (B staging)
#define APITCH 1040u       // A row pitch bytes (520 bf16, odd 16B chunks -> conflict-free)
#define BPITCH 272u        // B row pitch bytes (136 bf16)
#define AHI_OFF 0u
#define ALO_OFF 66560u           // 64*1040
#define B_OFF   133120u          // 2*66560
#define B_STG   34816u           // hi 17408 + lo 17408 per stage
#define T_OFF   202752u          // B_OFF + 2*34816
#define V_OFF   204800u
#define E_OFF   206848u
#define SMEM_TOTAL 207872        // E_OFF + 4*64*4

// ---------------- device scratch ----------------
__device__ float g_t[B_ * H_];
__device__ float g_e[B_ * S_];
__device__ float g_ctx[B_ * SPLIT * D_];
__device__ __nv_bfloat16 g_wsh[H_ * D_];   // Ws hi (row h, k contiguous)
__device__ __nv_bfloat16 g_wsl[H_ * D_];   // Ws lo

// ---------------- helpers ----------------
__device__ __forceinline__ uint32_t smem_u32(const void* p) {
    uint32_t a;
    asm("{ .reg .u64 t; cvta.to.shared.u64 t, %1; cvt.u32.u64 %0, t; }" : "=r"(a) : "l"(p));
    return a;
}
__device__ __forceinline__ uint32_t pack_bf16(float a, float b) {
    return (uint32_t)__bfloat16_as_ushort(__float2bfloat16(a)) |
           ((uint32_t)__bfloat16_as_ushort(__float2bfloat16(b)) << 16);
}

#define LDSM4(r0, r1, r2, r3, addr) \
    asm volatile("ldmatrix.sync.aligned.m8n8.x4.shared.b16 {%0,%1,%2,%3}, [%4];" \
                 : "=r"(r0), "=r"(r1), "=r"(r2), "=r"(r3) : "r"(addr))

#define MMA16816(c0, c1, c2, c3, a0, a1, a2, a3, b0, b1) \
    asm volatile("mma.sync.aligned.m16n8k16.row.col.f32.bf16.bf16.f32 " \
                 "{%0,%1,%2,%3}, {%4,%5,%6,%7}, {%8,%9}, {%0,%1,%2,%3};" \
                 : "+f"(c0), "+f"(c1), "+f"(c2), "+f"(c3) \
                 : "r"(a0), "r"(a1), "r"(a2), "r"(a3), "r"(b0), "r"(b1))

// ---------------- K0: split Ws into bf16 hi/lo ----------------
__global__ __launch_bounds__(256) void wsplit_kernel(const float* __restrict__ W) {
    int idx = blockIdx.x * 256 + threadIdx.x;      // over H*D
    int h = idx >> 9, d = idx & 511;
    float w = W[h * (2 * D_) + D_ + d];
    __nv_bfloat16 hi = __float2bfloat16(w);
    float lo = w - __bfloat162float(hi);
    g_wsh[idx] = hi;
    g_wsl[idx] = __float2bfloat16(lo);
}

// ---------------- K1: t[b,h] = targ[b,:] . W[h,:D] (fp32) ----------------
__global__ __launch_bounds__(512) void t_kernel(const float* __restrict__ targ,
                                                const float* __restrict__ W) {
    __shared__ float ts[D_];
    int b = blockIdx.x, h = threadIdx.x;
    ts[h] = targ[b * D_ + h];
    __syncthreads();
    const float* wr = W + (size_t)h * (2 * D_);
    float s = 0.0f;
#pragma unroll 8
    for (int d = 0; d < D_; d += 4) {
        float4 w4 = *(const float4*)(wr + d);
        s += ts[d] * w4.x + ts[d + 1] * w4.y + ts[d + 2] * w4.z + ts[d + 3] * w4.w;
    }
    g_t[b * H_ + h] = s;
}

// ---------------- K2: mma.sync bf16x3 GEMM + tanh + V-dot -> g_e ----------------
__global__ __launch_bounds__(256, 1) void gemm_e_mma(const float* __restrict__ src,
                                                     const float* __restrict__ V) {
    extern __shared__ __align__(1024) char smem[];
    const int tid = threadIdx.x;
    const int lane = tid & 31;
    const int wid = tid >> 5;
    const int m_base = blockIdx.x * MT;
    const int b = blockIdx.x >> 6;                 // 64 CTAs per batch

    float* ts = (float*)(smem + T_OFF);
    float* vs = (float*)(smem + V_OFF);
    float* e_sm = (float*)(smem + E_OFF);

    for (int i = tid; i < 512; i += 256) {
        ts[i] = g_t[b * H_ + i];
        vs[i] = V[i];
    }

    // stage A (64 x 512 fp32 -> bf16 hi/lo, padded rows)
    const float* Ab = src + (size_t)m_base * D_;
    for (int i = tid; i < 8192; i += 256) {        // 8192 float4
        int row = i >> 7;
        int c4 = (i & 127) << 2;
        float4 v = *(const float4*)(Ab + (size_t)row * D_ + c4);
        float h0 = __bfloat162float(__float2bfloat16(v.x));
        float h1 = __bfloat162float(__float2bfloat16(v.y));
        float h2 = __bfloat162float(__float2bfloat16(v.z));
        float h3 = __bfloat162float(__float2bfloat16(v.w));
        uint32_t off = (uint32_t)row * APITCH + (uint32_t)c4 * 2;
        *(uint2*)(smem + AHI_OFF + off) = make_uint2(pack_bf16(h0, h1), pack_bf16(h2, h3));
        *(uint2*)(smem + ALO_OFF + off) = make_uint2(pack_bf16(v.x - h0, v.y - h1),
                                                     pack_bf16(v.z - h2, v.w - h3));
    }
    __syncthreads();

    const uint32_t sb = smem_u32(smem);
    const int wm = wid >> 2;                       // 0..1
    const int wn = wid & 3;                        // 0..3
    const int g = lane >> 2;
    const int c2 = (lane & 3) * 2;

    // ldmatrix lane address components
    const uint32_t a_row  = (uint32_t)(wm * 32 + (lane & 15));
    const uint32_t a_koff = (uint32_t)((lane >> 4) * 8);
    const uint32_t b_row  = (uint32_t)(wn * 16 + (lane & 7) + ((lane >> 4) & 1) * 8);
    const uint32_t b_koff = (uint32_t)(((lane >> 3) & 1) * 8);

    const uint32_t a_hi_base = sb + AHI_OFF + a_row * APITCH + a_koff * 2;
    const uint32_t a_lo_base = sb + ALO_OFF + a_row * APITCH + a_koff * 2;

    float e_acc[4] = {0.f, 0.f, 0.f, 0.f};

    for (int nc = 0; nc < 8; ++nc) {
        // ---- stage B chunk ks=0 into buf 0 ----
        {
            const uint4* GH = (const uint4*)g_wsh;
            const uint4* GL = (const uint4*)g_wsl;
            char* dh = smem + B_OFF;               // buf 0 hi
            char* dl = dh + 17408;
            for (int i = tid; i < 1024; i += 256) {
                int n = i >> 4, c8 = i & 15;
                size_t gi = ((size_t)(nc * NCH + n) * D_) / 8 + c8;   // ks=0
                uint32_t off = (uint32_t)n * BPITCH + (uint32_t)c8 * 16;
                *(uint4*)(dh + off) = GH[gi];
                *(uint4*)(dl + off) = GL[gi];
            }
        }
        __syncthreads();

        float acc[2][2][4];
#pragma unroll
        for (int i = 0; i < 2; ++i)
#pragma unroll
            for (int j = 0; j < 2; ++j)
#pragma unroll
                for (int r = 0; r < 4; ++r) acc[i][j][r] = 0.f;

        for (int ks = 0; ks < 4; ++ks) {
            const int buf = ks & 1;
            // prefetch next B stage into buf^1
            if (ks < 3) {
                const uint4* GH = (const uint4*)g_wsh;
                const uint4* GL = (const uint4*)g_wsl;
                char* dh = smem + B_OFF + (buf ^ 1) * B_STG;
                char* dl = dh + 17408;
                for (int i = tid; i < 1024; i += 256) {
                    int n = i >> 4, c8 = i & 15;
                    size_t gi = ((size_t)(nc * NCH + n) * D_ + (size_t)(ks + 1) * KCH) / 8 + c8;
                    uint32_t off = (uint32_t)n * BPITCH + (uint32_t)c8 * 16;
                    *(uint4*)(dh + off) = GH[gi];
                    *(uint4*)(dl + off) = GL[gi];
                }
            }
            const uint32_t b_hi_base = sb + B_OFF + (uint32_t)buf * B_STG + b_row * BPITCH + b_koff * 2;
            const uint32_t b_lo_base = b_hi_base + 17408;
            const uint32_t a_kchunk = (uint32_t)(ks * KCH) * 2;   // bytes

#pragma unroll
            for (int kk = 0; kk < 8; ++kk) {
                const uint32_t kb = (uint32_t)kk * 32;
                uint32_t ah0[4], ah1[4], al0[4], al1[4];
                LDSM4(ah0[0], ah0[1], ah0[2], ah0[3], a_hi_base + a_kchunk + kb);
                LDSM4(ah1[0], ah1[1], ah1[2], ah1[3], a_hi_base + a_kchunk + kb + 16u * APITCH);
                LDSM4(al0[0], al0[1], al0[2], al0[3], a_lo_base + a_kchunk + kb);
                LDSM4(al1[0], al1[1], al1[2], al1[3], a_lo_base + a_kchunk + kb + 16u * APITCH);
                uint32_t bh[4], bl[4];
                LDSM4(bh[0], bh[1], bh[2], bh[3], b_hi_base + kb);
                LDSM4(bl[0], bl[1], bl[2], bl[3], b_lo_base + kb);

                // hi*hi
                MMA16816(acc[0][0][0], acc[0][0][1], acc[0][0][2], acc[0][0][3],
                         ah0[0], ah0[1], ah0[2], ah0[3], bh[0], bh[1]);
                MMA16816(acc[0][1][0], acc[0][1][1], acc[0][1][2], acc[0][1][3],
                         ah0[0], ah0[1], ah0[2], ah0[3], bh[2], bh[3]);
                MMA16816(acc[1][0][0], acc[1][0][1], acc[1][0][2], acc[1][0][3],
                         ah1[0], ah1[1], ah1[2], ah1[3], bh[0], bh[1]);
                MMA16816(acc[1][1][0], acc[1][1][1], acc[1][1][2], acc[1][1][3],
                         ah1[0], ah1[1], ah1[2], ah1[3], bh[2], bh[3]);
                // hi*lo
                MMA16816(acc[0][0][0], acc[0][0][1], acc[0][0][2], acc[0][0][3],
                         ah0[0], ah0[1], ah0[2], ah0[3], bl[0], bl[1]);
                MMA16816(acc[0][1][0], acc[0][1][1], acc[0][1][2], acc[0][1][3],
                         ah0[0], ah0[1], ah0[2], ah0[3], bl[2], bl[3]);
                MMA16816(acc[1][0][0], acc[1][0][1], acc[1][0][2], acc[1][0][3],
                         ah1[0], ah1[1], ah1[2], ah1[3], bl[0], bl[1]);
                MMA16816(acc[1][1][0], acc[1][1][1], acc[1][1][2], acc[1][1][3],
                         ah1[0], ah1[1], ah1[2], ah1[3], bl[2], bl[3]);
                // lo*hi
                MMA16816(acc[0][0][0], acc[0][0][1], acc[0][0][2], acc[0][0][3],
                         al0[0], al0[1], al0[2], al0[3], bh[0], bh[1]);
                MMA16816(acc[0][1][0], acc[0][1][1], acc[0][1][2], acc[0][1][3],
                         al0[0], al0[1], al0[2], al0[3], bh[2], bh[3]);
                MMA16816(acc[1][0][0], acc[1][0][1], acc[1][0][2], acc[1][0][3],
                         al1[0], al1[1], al1[2], al1[3], bh[0], bh[1]);
                MMA16816(acc[1][1][0], acc[1][1][1], acc[1][1][2], acc[1][1][3],
                         al1[0], al1[1], al1[2], al1[3], bh[2], bh[3]);
            }
            __syncthreads();
        }

        // ---- epilogue for this N chunk: e += V * tanh(acc + t) ----
#pragma unroll
        for (int mt = 0; mt < 2; ++mt) {
#pragma unroll
            for (int nt = 0; nt < 2; ++nt) {
                const int n0 = nc * NCH + wn * 16 + nt * 8 + c2;
                const float t0 = ts[n0], t1 = ts[n0 + 1];
                const float v0 = vs[n0], v1 = vs[n0 + 1];
#pragma unroll
                for (int r = 0; r < 4; ++r) {
                    const float tv = (r & 1) ? t1 : t0;
                    const float vv = (r & 1) ? v1 : v0;
                    float x = acc[mt][nt][r] + tv;
                    float ex = __expf(2.0f * x);
                    float th = 1.0f - __fdividef(2.0f, ex + 1.0f);
                    e_acc[mt * 2 + (r >> 1)] = fmaf(vv, th, e_acc[mt * 2 + (r >> 1)]);
                }
            }
        }
    }

    // reduce e over the 4 lanes sharing a row (c bits of lane)
#pragma unroll
    for (int j = 0; j < 4; ++j) {
        e_acc[j] += __shfl_xor_sync(0xffffffffu, e_acc[j], 1);
        e_acc[j] += __shfl_xor_sync(0xffffffffu, e_acc[j], 2);
    }
    if ((lane & 3) == 0) {
#pragma unroll
        for (int j = 0; j < 4; ++j) {
            int row = wm * 32 + (j >> 1) * 16 + (j & 1) * 8 + g;
            e_sm[wn * 64 + row] = e_acc[j];
        }
    }
    __syncthreads();
    if (tid < MT) {
        float s = e_sm[tid] + e_sm[64 + tid] + e_sm[128 + tid] + e_sm[192 + tid];
        g_e[m_base + tid] = s;
    }
}

// ---------------- K3: softmax ----------------
__global__ __launch_bounds__(256) void softmax_kernel(const float* __restrict__ mask,
                                                      float* __restrict__ out_att) {
    const int b = blockIdx.x;
    const int tid = threadIdx.x;
    const float* e = g_e + (size_t)b * S_;
    __shared__ float red[8];

    float vals[16];
    float mx = -1e30f;
#pragma unroll
    for (int i = 0; i < 16; ++i) {
        vals[i] = e[tid + i * 256];
        mx = fmaxf(mx, vals[i]);
    }
#pragma unroll
    for (int o = 16; o >= 1; o >>= 1) mx = fmaxf(mx, __shfl_xor_sync(0xffffffffu, mx, o));
    if ((tid & 31) == 0) red[tid >> 5] = mx;
    __syncthreads();
    float M = red[0];
#pragma unroll
    for (int i = 1; i < 8; ++i) M = fmaxf(M, red[i]);
    __syncthreads();

    float sum = 0.0f;
#pragma unroll
    for (int i = 0; i < 16; ++i) {
        vals[i] = expf(vals[i] - M);
        sum += vals[i];
    }
#pragma unroll
    for (int o = 16; o >= 1; o >>= 1) sum += __shfl_xor_sync(0xffffffffu, sum, o);
    if ((tid & 31) == 0) red[tid >> 5] = sum;
    __syncthreads();
    float Ssum = 0.0f;
#pragma unroll
    for (int i = 0; i < 8; ++i) Ssum += red[i];

    const float inv = 1.0f / Ssum;
    const float* mrow = mask + (size_t)b * S_;
    float* orow = out_att + (size_t)b * S_;
#pragma unroll
    for (int i = 0; i < 16; ++i) {
        int s = tid + i * 256;
        orow[s] = vals[i] * inv * mrow[s];
    }
}

// ---------------- K4: ctx partials ----------------
__global__ __launch_bounds__(512) void ctx_partial_kernel(const float* __restrict__ src,
                                                          const float* __restrict__ att) {
    __shared__ float aw[S_PER_SPLIT];
    const int b = blockIdx.x;
    const int sp = blockIdx.y;
    const int tid = threadIdx.x;
    if (tid < S_PER_SPLIT) aw[tid] = att[(size_t)b * S_ + sp * S_PER_SPLIT + tid];
    __syncthreads();

    const float* p = src + ((size_t)b * S_ + (size_t)sp * S_PER_SPLIT) * D_ + tid;
    float a0 = 0.f, a1 = 0.f, a2 = 0.f, a3 = 0.f;
#pragma unroll 4
    for (int s = 0; s < S_PER_SPLIT; s += 4) {
        a0 = fmaf(aw[s + 0], p[(size_t)(s + 0) * D_], a0);
        a1 = fmaf(aw[s + 1], p[(size_t)(s + 1) * D_], a1);
        a2 = fmaf(aw[s + 2], p[(size_t)(s + 2) * D_], a2);
        a3 = fmaf(aw[s + 3], p[(size_t)(s + 3) * D_], a3);
    }
    g_ctx[((size_t)b * SPLIT + sp) * D_ + tid] = (a0 + a1) + (a2 + a3);
}

// ---------------- K5: reduce + residual ----------------
__global__ __launch_bounds__(512) void reduce_kernel(const float* __restrict__ targ,
                                                     float* __restrict__ out_hidden) {
    const int b = blockIdx.x;
    const int d = threadIdx.x;
    float s = targ[b * D_ + d];
#pragma unroll
    for (int sp = 0; sp < SPLIT; ++sp) s += g_ctx[((size_t)b * SPLIT + sp) * D_ + d];
    out_hidden[b * D_ + d] = s;
}

// ---------------- launcher ----------------
extern "C" void kernel_launch(void* const* d_in, const int* in_sizes, int n_in,
                              void* d_out, int out_size) {
    const float* targ = (const float*)d_in[0];
    const float* src  = (const float*)d_in[1];
    const float* mask = (const float*)d_in[2];
    const float* W    = (const float*)d_in[3];
    const float* V    = (const float*)d_in[4];

    float* out = (float*)d_out;
    float* out_att    = out;
    float* out_hidden = out + B_ * S_;

    cudaFuncSetAttribute(gemm_e_mma, cudaFuncAttributeMaxDynamicSharedMemorySize, SMEM_TOTAL);

    wsplit_kernel<<<H_ * D_ / 256, 256>>>(W);
    t_kernel<<<B_, D_>>>(targ, W);
    gemm_e_mma<<<M_ / MT, 256, SMEM_TOTAL>>>(src, V);
    softmax_kernel<<<B_, 256>>>(mask, out_att);
    dim3 g4(B_, SPLIT);
    ctx_partial_kernel<<<g4, D_>>>(src, out_att);
    reduce_kernel<<<B_, D_>>>(targ, out_hidden);
}

// round 4
// speedup vs baseline: 2.0442x; 1.2651x over previous
#include <cuda_runtime.h>
#include <cuda_bf16.h>
#include <stdint.h>
#include <math.h>

// ---------------- problem constants ----------------
#define B_  32
#define S_  4096
#define D_  512
#define H_  512
#define M_  (B_ * S_)

#define SPLIT 32
#define S_PER_SPLIT 128

// gemm_e tiling
#define MT   64            // M rows per CTA
#define NCH  64            // N chunk
#define KCH  128           // K chunk (B staging)
#define NSTG 32            // total B stages = (512/NCH) * (512/KCH)
#define APITCH 1040u       // A row pitch bytes
#define BPITCH 272u        // B row pitch bytes
#define AHI_OFF 0u
#define ALO_OFF 66560u           // 64*1040
#define B_OFF   133120u          // 2*66560
#define B_HALF  17408u           // 64*272
#define B_STG   34816u           // hi + lo per stage buffer
#define T_OFF   202752u          // B_OFF + 2*B_STG
#define V_OFF   204800u
#define E_OFF   206848u
#define SMEM_TOTAL 207872

// ---------------- device scratch ----------------
__device__ float g_t[B_ * H_];
__device__ float g_e[B_ * S_];
__device__ float g_ctx[B_ * SPLIT * D_];
__device__ __nv_bfloat16 g_wsh[H_ * D_];   // Ws hi (row h, k contiguous)
__device__ __nv_bfloat16 g_wsl[H_ * D_];   // Ws lo

// ---------------- helpers ----------------
__device__ __forceinline__ uint32_t smem_u32(const void* p) {
    uint32_t a;
    asm("{ .reg .u64 t; cvta.to.shared.u64 t, %1; cvt.u32.u64 %0, t; }" : "=r"(a) : "l"(p));
    return a;
}
__device__ __forceinline__ uint32_t pack_bf16(float a, float b) {
    return (uint32_t)__bfloat16_as_ushort(__float2bfloat16(a)) |
           ((uint32_t)__bfloat16_as_ushort(__float2bfloat16(b)) << 16);
}
__device__ __forceinline__ void cp16(uint32_t dst, const void* src) {
    asm volatile("cp.async.cg.shared.global [%0], [%1], 16;" :: "r"(dst), "l"(src));
}
#define CP_COMMIT() asm volatile("cp.async.commit_group;" ::: "memory")
#define CP_WAIT(n)  asm volatile("cp.async.wait_group %0;" :: "n"(n) : "memory")

#define LDSM4(r0, r1, r2, r3, addr) \
    asm volatile("ldmatrix.sync.aligned.m8n8.x4.shared.b16 {%0,%1,%2,%3}, [%4];" \
                 : "=r"(r0), "=r"(r1), "=r"(r2), "=r"(r3) : "r"(addr))

#define MMA16816(c0, c1, c2, c3, a0, a1, a2, a3, b0, b1) \
    asm volatile("mma.sync.aligned.m16n8k16.row.col.f32.bf16.bf16.f32 " \
                 "{%0,%1,%2,%3}, {%4,%5,%6,%7}, {%8,%9}, {%0,%1,%2,%3};" \
                 : "+f"(c0), "+f"(c1), "+f"(c2), "+f"(c3) \
                 : "r"(a0), "r"(a1), "r"(a2), "r"(a3), "r"(b0), "r"(b1))

// ---------------- K0: split Ws into bf16 hi/lo ----------------
__global__ __launch_bounds__(256) void wsplit_kernel(const float* __restrict__ W) {
    int idx = blockIdx.x * 256 + threadIdx.x;
    int h = idx >> 9, d = idx & 511;
    float w = W[h * (2 * D_) + D_ + d];
    __nv_bfloat16 hi = __float2bfloat16(w);
    float lo = w - __bfloat162float(hi);
    g_wsh[idx] = hi;
    g_wsl[idx] = __float2bfloat16(lo);
}

// ---------------- K1: t[b,h] = targ[b,:] . W[h,:D] (fp32) ----------------
__global__ __launch_bounds__(512) void t_kernel(const float* __restrict__ targ,
                                                const float* __restrict__ W) {
    __shared__ float ts[D_];
    int b = blockIdx.x, h = threadIdx.x;
    ts[h] = targ[b * D_ + h];
    __syncthreads();
    const float* wr = W + (size_t)h * (2 * D_);
    float s = 0.0f;
#pragma unroll 8
    for (int d = 0; d < D_; d += 4) {
        float4 w4 = *(const float4*)(wr + d);
        s += ts[d] * w4.x + ts[d + 1] * w4.y + ts[d + 2] * w4.z + ts[d + 3] * w4.w;
    }
    g_t[b * H_ + h] = s;
}

// ---------------- K2: mma.sync bf16x3 GEMM + tanh + V-dot, cp.async pipelined ----
__global__ __launch_bounds__(256, 1) void gemm_e_mma(const float* __restrict__ src,
                                                     const float* __restrict__ V) {
    extern __shared__ __align__(1024) char smem[];
    const int tid = threadIdx.x;
    const int lane = tid & 31;
    const int wid = tid >> 5;
    const int m_base = blockIdx.x * MT;
    const int b = blockIdx.x >> 6;

    float* ts = (float*)(smem + T_OFF);
    float* vs = (float*)(smem + V_OFF);
    float* e_sm = (float*)(smem + E_OFF);
    const uint32_t sb = smem_u32(smem);

    for (int i = tid; i < 512; i += 256) {
        ts[i] = g_t[b * H_ + i];
        vs[i] = V[i];
    }

    // ---- issue B stage 0 via cp.async (overlaps A conversion below) ----
    // stage s: nc = s>>2, ks = s&3. 2048 x 16B per stage (hi + lo).
    const char* GHB = (const char*)g_wsh;
    const char* GLB = (const char*)g_wsl;
    {
        const uint32_t d0 = sb + B_OFF;            // buf 0
#pragma unroll
        for (int r = 0; r < 8; ++r) {
            int i = tid + r * 256;                 // 0..2047
            int half = i >> 10, j = i & 1023;
            int n = j >> 4, c8 = j & 15;
            const char* srcp = (half ? GLB : GHB) + (size_t)n * 1024 + (size_t)c8 * 16;
            cp16(d0 + (uint32_t)half * B_HALF + (uint32_t)n * BPITCH + (uint32_t)c8 * 16, srcp);
        }
        CP_COMMIT();
    }

    // ---- stage A (64 x 512 fp32 -> bf16 hi/lo, resident) ----
    const float* Ab = src + (size_t)m_base * D_;
    for (int i = tid; i < 8192; i += 256) {
        int row = i >> 7;
        int c4 = (i & 127) << 2;
        float4 v = *(const float4*)(Ab + (size_t)row * D_ + c4);
        float h0 = __bfloat162float(__float2bfloat16(v.x));
        float h1 = __bfloat162float(__float2bfloat16(v.y));
        float h2 = __bfloat162float(__float2bfloat16(v.z));
        float h3 = __bfloat162float(__float2bfloat16(v.w));
        uint32_t off = (uint32_t)row * APITCH + (uint32_t)c4 * 2;
        *(uint2*)(smem + AHI_OFF + off) = make_uint2(pack_bf16(h0, h1), pack_bf16(h2, h3));
        *(uint2*)(smem + ALO_OFF + off) = make_uint2(pack_bf16(v.x - h0, v.y - h1),
                                                     pack_bf16(v.z - h2, v.w - h3));
    }

    const int wm = wid >> 2;                       // 0..1
    const int wn = wid & 3;                        // 0..3
    const int g = lane >> 2;
    const int c2 = (lane & 3) * 2;

    const uint32_t a_row  = (uint32_t)(wm * 32 + (lane & 15));
    const uint32_t a_koff = (uint32_t)((lane >> 4) * 8);
    const uint32_t b_row  = (uint32_t)(wn * 16 + (lane & 7) + ((lane >> 4) & 1) * 8);
    const uint32_t b_koff = (uint32_t)(((lane >> 3) & 1) * 8);

    const uint32_t a_hi_base = sb + AHI_OFF + a_row * APITCH + a_koff * 2;
    const uint32_t a_lo_base = sb + ALO_OFF + a_row * APITCH + a_koff * 2;

    float e_acc[4] = {0.f, 0.f, 0.f, 0.f};
    float acc[2][2][4];

    for (int s = 0; s < NSTG; ++s) {
        const int nc = s >> 2;
        const int ks = s & 3;
        const int buf = s & 1;

        // issue load(s+1) into buf^1 (consumed buffer was freed by prior sync)
        if (s + 1 < NSTG) {
            const int nc1 = (s + 1) >> 2;
            const int ks1 = (s + 1) & 3;
            const uint32_t d1 = sb + B_OFF + (uint32_t)(buf ^ 1) * B_STG;
            const size_t gbase = (size_t)nc1 * NCH * 1024 + (size_t)ks1 * 256;
#pragma unroll
            for (int r = 0; r < 8; ++r) {
                int i = tid + r * 256;
                int half = i >> 10, j = i & 1023;
                int n = j >> 4, c8 = j & 15;
                const char* srcp = (half ? GLB : GHB) + gbase + (size_t)n * 1024 + (size_t)c8 * 16;
                cp16(d1 + (uint32_t)half * B_HALF + (uint32_t)n * BPITCH + (uint32_t)c8 * 16, srcp);
            }
            CP_COMMIT();
            CP_WAIT(1);    // stage s resident, stage s+1 in flight
        } else {
            CP_WAIT(0);
        }
        __syncthreads();   // stage s visible to all; A staged (first iter)

        if (ks == 0) {
#pragma unroll
            for (int i = 0; i < 2; ++i)
#pragma unroll
                for (int j = 0; j < 2; ++j)
#pragma unroll
                    for (int r = 0; r < 4; ++r) acc[i][j][r] = 0.f;
        }

        const uint32_t b_hi_base = sb + B_OFF + (uint32_t)buf * B_STG + b_row * BPITCH + b_koff * 2;
        const uint32_t b_lo_base = b_hi_base + B_HALF;
        const uint32_t a_kchunk = (uint32_t)(ks * KCH) * 2;

#pragma unroll
        for (int kk = 0; kk < 8; ++kk) {
            const uint32_t kb = (uint32_t)kk * 32;
            uint32_t ah0[4], ah1[4], al0[4], al1[4];
            LDSM4(ah0[0], ah0[1], ah0[2], ah0[3], a_hi_base + a_kchunk + kb);
            LDSM4(ah1[0], ah1[1], ah1[2], ah1[3], a_hi_base + a_kchunk + kb + 16u * APITCH);
            LDSM4(al0[0], al0[1], al0[2], al0[3], a_lo_base + a_kchunk + kb);
            LDSM4(al1[0], al1[1], al1[2], al1[3], a_lo_base + a_kchunk + kb + 16u * APITCH);
            uint32_t bh[4], bl[4];
            LDSM4(bh[0], bh[1], bh[2], bh[3], b_hi_base + kb);
            LDSM4(bl[0], bl[1], bl[2], bl[3], b_lo_base + kb);

            MMA16816(acc[0][0][0], acc[0][0][1], acc[0][0][2], acc[0][0][3],
                     ah0[0], ah0[1], ah0[2], ah0[3], bh[0], bh[1]);
            MMA16816(acc[0][1][0], acc[0][1][1], acc[0][1][2], acc[0][1][3],
                     ah0[0], ah0[1], ah0[2], ah0[3], bh[2], bh[3]);
            MMA16816(acc[1][0][0], acc[1][0][1], acc[1][0][2], acc[1][0][3],
                     ah1[0], ah1[1], ah1[2], ah1[3], bh[0], bh[1]);
            MMA16816(acc[1][1][0], acc[1][1][1], acc[1][1][2], acc[1][1][3],
                     ah1[0], ah1[1], ah1[2], ah1[3], bh[2], bh[3]);

            MMA16816(acc[0][0][0], acc[0][0][1], acc[0][0][2], acc[0][0][3],
                     ah0[0], ah0[1], ah0[2], ah0[3], bl[0], bl[1]);
            MMA16816(acc[0][1][0], acc[0][1][1], acc[0][1][2], acc[0][1][3],
                     ah0[0], ah0[1], ah0[2], ah0[3], bl[2], bl[3]);
            MMA16816(acc[1][0][0], acc[1][0][1], acc[1][0][2], acc[1][0][3],
                     ah1[0], ah1[1], ah1[2], ah1[3], bl[0], bl[1]);
            MMA16816(acc[1][1][0], acc[1][1][1], acc[1][1][2], acc[1][1][3],
                     ah1[0], ah1[1], ah1[2], ah1[3], bl[2], bl[3]);

            MMA16816(acc[0][0][0], acc[0][0][1], acc[0][0][2], acc[0][0][3],
                     al0[0], al0[1], al0[2], al0[3], bh[0], bh[1]);
            MMA16816(acc[0][1][0], acc[0][1][1], acc[0][1][2], acc[0][1][3],
                     al0[0], al0[1], al0[2], al0[3], bh[2], bh[3]);
            MMA16816(acc[1][0][0], acc[1][0][1], acc[1][0][2], acc[1][0][3],
                     al1[0], al1[1], al1[2], al1[3], bh[0], bh[1]);
            MMA16816(acc[1][1][0], acc[1][1][1], acc[1][1][2], acc[1][1][3],
                     al1[0], al1[1], al1[2], al1[3], bh[2], bh[3]);
        }
        __syncthreads();   // all warps done with buf before next overwrite

        if (ks == 3) {
            // epilogue for this nc: e += V * tanh(acc + t)
#pragma unroll
            for (int mt = 0; mt < 2; ++mt) {
#pragma unroll
                for (int nt = 0; nt < 2; ++nt) {
                    const int n0 = nc * NCH + wn * 16 + nt * 8 + c2;
                    const float t0 = ts[n0], t1 = ts[n0 + 1];
                    const float v0 = vs[n0], v1 = vs[n0 + 1];
#pragma unroll
                    for (int r = 0; r < 4; ++r) {
                        const float tv = (r & 1) ? t1 : t0;
                        const float vv = (r & 1) ? v1 : v0;
                        float x = acc[mt][nt][r] + tv;
                        float ex = __expf(2.0f * x);
                        float th = 1.0f - __fdividef(2.0f, ex + 1.0f);
                        e_acc[mt * 2 + (r >> 1)] = fmaf(vv, th, e_acc[mt * 2 + (r >> 1)]);
                    }
                }
            }
        }
    }

    // reduce e over the 4 lanes sharing a row
#pragma unroll
    for (int j = 0; j < 4; ++j) {
        e_acc[j] += __shfl_xor_sync(0xffffffffu, e_acc[j], 1);
        e_acc[j] += __shfl_xor_sync(0xffffffffu, e_acc[j], 2);
    }
    if ((lane & 3) == 0) {
#pragma unroll
        for (int j = 0; j < 4; ++j) {
            int row = wm * 32 + (j >> 1) * 16 + (j & 1) * 8 + g;
            e_sm[wn * 64 + row] = e_acc[j];
        }
    }
    __syncthreads();
    if (tid < MT) {
        float s = e_sm[tid] + e_sm[64 + tid] + e_sm[128 + tid] + e_sm[192 + tid];
        g_e[m_base + tid] = s;
    }
}

// ---------------- K3: softmax ----------------
__global__ __launch_bounds__(256) void softmax_kernel(const float* __restrict__ mask,
                                                      float* __restrict__ out_att) {
    const int b = blockIdx.x;
    const int tid = threadIdx.x;
    const float* e = g_e + (size_t)b * S_;
    __shared__ float red[8];

    float vals[16];
    float mx = -1e30f;
#pragma unroll
    for (int i = 0; i < 16; ++i) {
        vals[i] = e[tid + i * 256];
        mx = fmaxf(mx, vals[i]);
    }
#pragma unroll
    for (int o = 16; o >= 1; o >>= 1) mx = fmaxf(mx, __shfl_xor_sync(0xffffffffu, mx, o));
    if ((tid & 31) == 0) red[tid >> 5] = mx;
    __syncthreads();
    float M = red[0];
#pragma unroll
    for (int i = 1; i < 8; ++i) M = fmaxf(M, red[i]);
    __syncthreads();

    float sum = 0.0f;
#pragma unroll
    for (int i = 0; i < 16; ++i) {
        vals[i] = expf(vals[i] - M);
        sum += vals[i];
    }
#pragma unroll
    for (int o = 16; o >= 1; o >>= 1) sum += __shfl_xor_sync(0xffffffffu, sum, o);
    if ((tid & 31) == 0) red[tid >> 5] = sum;
    __syncthreads();
    float Ssum = 0.0f;
#pragma unroll
    for (int i = 0; i < 8; ++i) Ssum += red[i];

    const float inv = 1.0f / Ssum;
    const float* mrow = mask + (size_t)b * S_;
    float* orow = out_att + (size_t)b * S_;
#pragma unroll
    for (int i = 0; i < 16; ++i) {
        int s = tid + i * 256;
        orow[s] = vals[i] * inv * mrow[s];
    }
}

// ---------------- K4: ctx partials ----------------
__global__ __launch_bounds__(512) void ctx_partial_kernel(const float* __restrict__ src,
                                                          const float* __restrict__ att) {
    __shared__ float aw[S_PER_SPLIT];
    const int b = blockIdx.x;
    const int sp = blockIdx.y;
    const int tid = threadIdx.x;
    if (tid < S_PER_SPLIT) aw[tid] = att[(size_t)b * S_ + sp * S_PER_SPLIT + tid];
    __syncthreads();

    const float* p = src + ((size_t)b * S_ + (size_t)sp * S_PER_SPLIT) * D_ + tid;
    float a0 = 0.f, a1 = 0.f, a2 = 0.f, a3 = 0.f;
#pragma unroll 4
    for (int s = 0; s < S_PER_SPLIT; s += 4) {
        a0 = fmaf(aw[s + 0], p[(size_t)(s + 0) * D_], a0);
        a1 = fmaf(aw[s + 1], p[(size_t)(s + 1) * D_], a1);
        a2 = fmaf(aw[s + 2], p[(size_t)(s + 2) * D_], a2);
        a3 = fmaf(aw[s + 3], p[(size_t)(s + 3) * D_], a3);
    }
    g_ctx[((size_t)b * SPLIT + sp) * D_ + tid] = (a0 + a1) + (a2 + a3);
}

// ---------------- K5: reduce + residual ----------------
__global__ __launch_bounds__(512) void reduce_kernel(const float* __restrict__ targ,
                                                     float* __restrict__ out_hidden) {
    const int b = blockIdx.x;
    const int d = threadIdx.x;
    float s = targ[b * D_ + d];
#pragma unroll
    for (int sp = 0; sp < SPLIT; ++sp) s += g_ctx[((size_t)b * SPLIT + sp) * D_ + d];
    out_hidden[b * D_ + d] = s;
}

// ---------------- launcher ----------------
extern "C" void kernel_launch(void* const* d_in, const int* in_sizes, int n_in,
                              void* d_out, int out_size) {
    const float* targ = (const float*)d_in[0];
    const float* src  = (const float*)d_in[1];
    const float* mask = (const float*)d_in[2];
    const float* W    = (const float*)d_in[3];
    const float* V    = (const float*)d_in[4];

    float* out = (float*)d_out;
    float* out_att    = out;
    float* out_hidden = out + B_ * S_;

    cudaFuncSetAttribute(gemm_e_mma, cudaFuncAttributeMaxDynamicSharedMemorySize, SMEM_TOTAL);

    wsplit_kernel<<<H_ * D_ / 256, 256>>>(W);
    t_kernel<<<B_, D_>>>(targ, W);
    gemm_e_mma<<<M_ / MT, 256, SMEM_TOTAL>>>(src, V);
    softmax_kernel<<<B_, 256>>>(mask, out_att);
    dim3 g4(B_, SPLIT);
    ctx_partial_kernel<<<g4, D_>>>(src, out_att);
    reduce_kernel<<<B_, D_>>>(targ, out_hidden);
}